// round 10
// baseline (speedup 1.0000x reference)
#include <cuda_runtime.h>
#include <cuda_bf16.h>
#include <cstdint>

#define N_NODES 50000
#define N_EDGES 800000
#define D       128
#define N_GR    64
#define NB_SCAN 196   // ceil(50000/256)

// -------- device scratch (no allocations allowed) --------
__device__ unsigned long long g_dcnt[N_NODES];   // fixed-point deg (low48) + count (high16)
__device__ float    g_dinv[N_NODES];
__device__ int      g_cnt [N_NODES];
__device__ int      g_off [N_NODES + 1];
__device__ int      g_bsum[256];
__device__ int      g_rank[N_EDGES];        // rank of edge within its target node
__device__ uint2    g_edge[N_EDGES];        // {src, norm-bits} per CSR slot
__device__ uint32_t g_bufA[N_NODES * 64];   // GEMM output, bf16x2-packed (gathered)
__device__ uint32_t g_bufB[N_NODES * 64];   // h1, bf16x2-packed (read seq. by GEMM2)
__device__ float    g_pool[N_GR * D];
__device__ float    g_wr1[128 * 128];       // tf32-rounded W1 ([k][n])
__device__ float    g_wr2[128 * 128];       // tf32-rounded W2 ([k][n])

#define FIXSCALE 268435456.0f               // 2^28

// ---------------- helpers ----------------
__device__ __forceinline__ float tf32r(float x) {
    uint32_t u;
    asm("cvt.rna.tf32.f32 %0, %1;" : "=r"(u) : "f"(x));
    return __uint_as_float(u);
}

__device__ __forceinline__ uint32_t packbf(float x, float y) {
    __nv_bfloat162 h = __floats2bfloat162_rn(x, y);
    return *reinterpret_cast<uint32_t*>(&h);
}

__device__ __forceinline__ float2 u2f2(uint32_t u) {
    __nv_bfloat162 h = *reinterpret_cast<__nv_bfloat162*>(&u);
    return __bfloat1622float2(h);
}

__device__ __forceinline__ float4 u2f4(uint2 u) {
    float2 a = u2f2(u.x);
    float2 b = u2f2(u.y);
    return make_float4(a.x, a.y, b.x, b.y);
}

__device__ __forceinline__ void mma_tf32(float* c, const uint32_t* a, const uint32_t* b) {
    asm volatile("mma.sync.aligned.m16n8k8.row.col.f32.tf32.tf32.f32 "
                 "{%0,%1,%2,%3}, {%4,%5,%6,%7}, {%8,%9}, {%0,%1,%2,%3};"
                 : "+f"(c[0]), "+f"(c[1]), "+f"(c[2]), "+f"(c[3])
                 : "r"(a[0]), "r"(a[1]), "r"(a[2]), "r"(a[3]),
                   "r"(b[0]), "r"(b[1]));
}

// -------- init accumulators + tf32-round weights (runs every replay) --------
__global__ void init_kernel(const float* __restrict__ W1,
                            const float* __restrict__ W2) {
    int i = blockIdx.x * blockDim.x + threadIdx.x;
    if (i < N_NODES) g_dcnt[i] = 0ULL;
    if (i < 128 * 128) { g_wr1[i] = tf32r(W1[i]); g_wr2[i] = tf32r(W2[i]); }
    if (i < N_GR * D) g_pool[i] = 0.0f;
}

// -------- per-edge: one 64-bit atomic; returned old value gives the rank ----
__global__ void edge_deg_kernel(const int* __restrict__ ei,
                                const float* __restrict__ ew) {
    int e = blockIdx.x * blockDim.x + threadIdx.x;
    if (e >= N_EDGES) return;
    int c = ei[N_EDGES + e];          // target node
    unsigned long long v = (1ULL << 48)
        | (unsigned long long)(long long)llrintf(ew[e] * FIXSCALE);
    unsigned long long old = atomicAdd(&g_dcnt[c], v);
    g_rank[e] = (int)(old >> 48);
}

// -------- scan1 fused with dinv: extract counts, dinv, block sums --------
__global__ void scan1_kernel() {
    __shared__ int s[256];
    int t = threadIdx.x;
    int i = blockIdx.x * 256 + t;
    int v = 0;
    if (i < N_NODES) {
        unsigned long long p = g_dcnt[i];
        v = (int)(p >> 48);
        g_cnt[i] = v;
        float deg = 1.0f + (float)(long long)(p & 0xFFFFFFFFFFFFULL) * (1.0f / FIXSCALE);
        g_dinv[i] = rsqrtf(deg);
    }
    s[t] = v;
    __syncthreads();
    for (int d = 128; d > 0; d >>= 1) {
        if (t < d) s[t] += s[t + d];
        __syncthreads();
    }
    if (t == 0) g_bsum[blockIdx.x] = s[0];
}

__global__ void scan2_kernel() {
    __shared__ int s[256];
    int t = threadIdx.x;
    int v = (t < NB_SCAN) ? g_bsum[t] : 0;
    s[t] = v;
    __syncthreads();
    for (int d = 1; d < 256; d <<= 1) {
        int u = (t >= d) ? s[t - d] : 0;
        __syncthreads();
        s[t] += u;
        __syncthreads();
    }
    if (t < NB_SCAN) g_bsum[t] = s[t] - v;
}

__global__ void scan3_kernel() {
    __shared__ int s[256];
    int t = threadIdx.x;
    int i = blockIdx.x * 256 + t;
    int v = (i < N_NODES) ? g_cnt[i] : 0;
    s[t] = v;
    __syncthreads();
    for (int d = 1; d < 256; d <<= 1) {
        int u = (t >= d) ? s[t - d] : 0;
        __syncthreads();
        s[t] += u;
        __syncthreads();
    }
    int base = g_bsum[blockIdx.x];
    if (i < N_NODES) g_off[i] = base + s[t] - v;
    if (i == N_NODES - 1) g_off[N_NODES] = base + s[t];
}

// -------- fill CSR: atomic-free using precomputed ranks --------
__global__ void fill_kernel(const int* __restrict__ ei,
                            const float* __restrict__ ew) {
    int e = blockIdx.x * blockDim.x + threadIdx.x;
    if (e >= N_EDGES) return;
    int r = ei[e];
    int c = ei[N_EDGES + e];
    int pos = g_off[c] + g_rank[e];
    float nrm = g_dinv[r] * ew[e] * g_dinv[c];
    g_edge[pos] = make_uint2((uint32_t)r, __float_as_uint(nrm));
}

// -------- tf32 mma.sync GEMM: g_bufA(bf16)[64-tile,128] = X-tile @ W --------
#define BM 64
#define XS_STRIDE 132
#define GEMM_SMEM_BYTES ((BM + 128) * XS_STRIDE * 4)

template <bool BF>
__global__ __launch_bounds__(256, 2) void gemm_mma(const float* __restrict__ Xext) {
    extern __shared__ float sh[];
    float* Xs = sh;                       // [64][132]
    float* Ws = sh + BM * XS_STRIDE;      // [128][132]  (W[k][n])

    const float* Wr = BF ? g_wr2 : g_wr1;

    const int tid = threadIdx.x;
    const int rowBase = blockIdx.x * BM;

#pragma unroll
    for (int i = 0; i < 8; i++) {
        int q = tid + 256 * i;            // 0..2047
        int r = q >> 5, c4 = q & 31;
        int rg = rowBase + r; if (rg >= N_NODES) rg = N_NODES - 1;
        float4 v;
        if (BF) {
            v = u2f4(reinterpret_cast<const uint2*>(g_bufB)[rg * 32 + c4]);
        } else {
            v = reinterpret_cast<const float4*>(Xext)[rg * 32 + c4];
        }
        float* d = &Xs[r * XS_STRIDE + c4 * 4];
        d[0] = tf32r(v.x); d[1] = tf32r(v.y); d[2] = tf32r(v.z); d[3] = tf32r(v.w);
    }
    const float4* W4 = reinterpret_cast<const float4*>(Wr);
#pragma unroll
    for (int i = 0; i < 16; i++) {
        int q = tid + 256 * i;            // 0..4095
        int r = q >> 5, c4 = q & 31;
        *reinterpret_cast<float4*>(&Ws[r * XS_STRIDE + c4 * 4]) = W4[q];
    }
    __syncthreads();

    const int lane = tid & 31, wid = tid >> 5;
    const int g = lane >> 2, t = lane & 3;
    const int mw = (wid >> 2) * 32;       // warp row offset (0/32)
    const int nw = (wid & 3) * 32;        // warp col offset (0/32/64/96)

    float c[2][4][4];
#pragma unroll
    for (int mt = 0; mt < 2; mt++)
#pragma unroll
        for (int nt = 0; nt < 4; nt++)
#pragma unroll
            for (int j = 0; j < 4; j++) c[mt][nt][j] = 0.f;

#pragma unroll 4
    for (int k0 = 0; k0 < 128; k0 += 8) {
        uint32_t a[2][4], b[4][2];
#pragma unroll
        for (int mt = 0; mt < 2; mt++) {
            const float* base = &Xs[(mw + mt * 16 + g) * XS_STRIDE + k0 + t];
            a[mt][0] = __float_as_uint(base[0]);
            a[mt][1] = __float_as_uint(base[8 * XS_STRIDE]);
            a[mt][2] = __float_as_uint(base[4]);
            a[mt][3] = __float_as_uint(base[8 * XS_STRIDE + 4]);
        }
#pragma unroll
        for (int nt = 0; nt < 4; nt++) {
            const float* bb = &Ws[(k0 + t) * XS_STRIDE + nw + nt * 8 + g];
            b[nt][0] = __float_as_uint(bb[0]);
            b[nt][1] = __float_as_uint(bb[4 * XS_STRIDE]);
        }
#pragma unroll
        for (int mt = 0; mt < 2; mt++)
#pragma unroll
            for (int nt = 0; nt < 4; nt++)
                mma_tf32(c[mt][nt], a[mt], b[nt]);
    }

#pragma unroll
    for (int mt = 0; mt < 2; mt++) {
        int row = rowBase + mw + mt * 16 + g;
#pragma unroll
        for (int nt = 0; nt < 4; nt++) {
            int ci = ((nw + nt * 8) >> 1) + t;      // bf16x2 column index
            if (row < N_NODES)
                g_bufA[row * 64 + ci] = packbf(c[mt][nt][0], c[mt][nt][1]);
            if (row + 8 < N_NODES)
                g_bufA[(row + 8) * 64 + ci] = packbf(c[mt][nt][2], c[mt][nt][3]);
        }
    }
}

// fma 8 features (one uint4 = 4 bf16x2) into acc[0..7]
#define AGG_FMA8(W_, R_)                                                     \
    {   float2 p0 = u2f2((R_).x), p1 = u2f2((R_).y);                         \
        float2 p2 = u2f2((R_).z), p3 = u2f2((R_).w);                         \
        acc[0] = fmaf((W_), p0.x, acc[0]); acc[1] = fmaf((W_), p0.y, acc[1]);\
        acc[2] = fmaf((W_), p1.x, acc[2]); acc[3] = fmaf((W_), p1.y, acc[3]);\
        acc[4] = fmaf((W_), p2.x, acc[4]); acc[5] = fmaf((W_), p2.y, acc[5]);\
        acc[6] = fmaf((W_), p3.x, acc[6]); acc[7] = fmaf((W_), p3.y, acc[7]); }

// -------- aggregation: warp per node; half-warps process alternating edges --
// each lane gathers 16B (8 features) of one row -> 2 rows in flight per warp op
template <bool POOL>
__global__ __launch_bounds__(256) void agg_kernel(const float* __restrict__ bias,
                                                  const int* __restrict__ batch) {
    const int node = blockIdx.x * 8 + (threadIdx.x >> 5);
    const int lane = threadIdx.x & 31;
    const int half = lane >> 4;           // 0 or 1
    const int col  = lane & 15;           // uint4 column within row
    const uint4* in16 = reinterpret_cast<const uint4*>(g_bufA);

    float acc[8];
    {
        // self-loop term only on half 0 (halves are summed at the end)
        uint4 sv = in16[node * 16 + col];
        float di = g_dinv[node];
        float s2 = (half == 0) ? di * di : 0.0f;
        float2 p0 = u2f2(sv.x), p1 = u2f2(sv.y), p2 = u2f2(sv.z), p3 = u2f2(sv.w);
        acc[0] = s2 * p0.x; acc[1] = s2 * p0.y;
        acc[2] = s2 * p1.x; acc[3] = s2 * p1.y;
        acc[4] = s2 * p2.x; acc[5] = s2 * p2.y;
        acc[6] = s2 * p3.x; acc[7] = s2 * p3.y;
    }

    int e  = g_off[node];
    int e1 = g_off[node + 1];
    // 4 edges per iteration: halves take {e+half, e+2+half}
    for (; e + 3 < e1; e += 4) {
        uint2 ma = g_edge[e + half];
        uint2 mb = g_edge[e + 2 + half];
        uint4 ra = in16[ma.x * 16 + col];
        uint4 rb = in16[mb.x * 16 + col];
        float wa = __uint_as_float(ma.y);
        float wb = __uint_as_float(mb.y);
        AGG_FMA8(wa, ra);
        AGG_FMA8(wb, rb);
    }
    for (; e + 1 < e1; e += 2) {
        uint2 m = g_edge[e + half];
        uint4 r = in16[m.x * 16 + col];
        AGG_FMA8(__uint_as_float(m.y), r);
    }
    if (e < e1 && half == 0) {
        uint2 m = g_edge[e];
        uint4 r = in16[m.x * 16 + col];
        AGG_FMA8(__uint_as_float(m.y), r);
    }

    // combine the two halves
#pragma unroll
    for (int j = 0; j < 8; j++)
        acc[j] += __shfl_xor_sync(0xFFFFFFFFu, acc[j], 16);

    // bias + relu (features col*8 .. col*8+7)
    float4 b0 = reinterpret_cast<const float4*>(bias)[col * 2];
    float4 b1 = reinterpret_cast<const float4*>(bias)[col * 2 + 1];
    acc[0] = fmaxf(acc[0] + b0.x, 0.f); acc[1] = fmaxf(acc[1] + b0.y, 0.f);
    acc[2] = fmaxf(acc[2] + b0.z, 0.f); acc[3] = fmaxf(acc[3] + b0.w, 0.f);
    acc[4] = fmaxf(acc[4] + b1.x, 0.f); acc[5] = fmaxf(acc[5] + b1.y, 0.f);
    acc[6] = fmaxf(acc[6] + b1.z, 0.f); acc[7] = fmaxf(acc[7] + b1.w, 0.f);

    if (half == 0) {
        if (POOL) {
            int g = batch[node];
            float* p = &g_pool[g * D + col * 8];
#pragma unroll
            for (int j = 0; j < 8; j++) atomicAdd(p + j, acc[j]);
        } else {
            uint4 o;
            o.x = packbf(acc[0], acc[1]);
            o.y = packbf(acc[2], acc[3]);
            o.z = packbf(acc[4], acc[5]);
            o.w = packbf(acc[6], acc[7]);
            reinterpret_cast<uint4*>(g_bufB)[node * 16 + col] = o;
        }
    }
}

// -------- head: count via binary search on sorted batch (no atomics) --------
__global__ void final_kernel(const float* __restrict__ Wh,
                             const float* __restrict__ bh,
                             const int* __restrict__ batch,
                             float* __restrict__ out) {
    __shared__ float red[128];
    const int g = blockIdx.x;
    const int t = threadIdx.x;

    int lo = 0, hi = N_NODES;
    while (lo < hi) { int m = (lo + hi) >> 1; if (batch[m] < g) lo = m + 1; else hi = m; }
    int start = lo;
    hi = N_NODES;
    while (lo < hi) { int m = (lo + hi) >> 1; if (batch[m] < g + 1) lo = m + 1; else hi = m; }
    float c = fmaxf((float)(lo - start), 1.0f);

    float v = (g_pool[g * D + t] / c) * Wh[t];
    red[t] = v;
    __syncthreads();
    for (int s = 64; s > 0; s >>= 1) {
        if (t < s) red[t] += red[t + s];
        __syncthreads();
    }
    if (t == 0) out[g] = red[0] + bh[0];
}

extern "C" void kernel_launch(void* const* d_in, const int* in_sizes, int n_in,
                              void* d_out, int out_size) {
    const float* x     = (const float*)d_in[0];
    const float* ew    = (const float*)d_in[1];
    const float* W1    = (const float*)d_in[2];
    const float* b1    = (const float*)d_in[3];
    const float* W2    = (const float*)d_in[4];
    const float* b2    = (const float*)d_in[5];
    const float* Wh    = (const float*)d_in[6];
    const float* bh    = (const float*)d_in[7];
    const int*   ei    = (const int*)d_in[8];
    const int*   batch = (const int*)d_in[9];
    float*       out   = (float*)d_out;

    const int NB_N = (N_NODES + 255) / 256;   // 196
    const int NB_E = (N_EDGES + 255) / 256;   // 3125
    const int NB_G = (N_NODES + BM - 1) / BM; // 782

    static bool ready = false;
    static cudaStream_t s1;
    static cudaEvent_t evA, evB;
    if (!ready) {
        cudaFuncSetAttribute(gemm_mma<false>, cudaFuncAttributeMaxDynamicSharedMemorySize,
                             GEMM_SMEM_BYTES);
        cudaFuncSetAttribute(gemm_mma<true>, cudaFuncAttributeMaxDynamicSharedMemorySize,
                             GEMM_SMEM_BYTES);
        cudaStreamCreateWithFlags(&s1, cudaStreamNonBlocking);
        cudaEventCreateWithFlags(&evA, cudaEventDisableTiming);
        cudaEventCreateWithFlags(&evB, cudaEventDisableTiming);
        ready = true;
    }

    // s0 = legacy default stream (the one being captured)
    init_kernel<<<NB_N, 256>>>(W1, W2);
    cudaEventRecord(evA, 0);

    // branch: layer-1 GEMM on s1, concurrent with CSR build on s0
    cudaStreamWaitEvent(s1, evA, 0);
    gemm_mma<false><<<NB_G, 256, GEMM_SMEM_BYTES, s1>>>(x);
    cudaEventRecord(evB, s1);

    edge_deg_kernel<<<NB_E, 256>>>(ei, ew);
    scan1_kernel<<<NB_SCAN, 256>>>();
    scan2_kernel<<<1, 256>>>();
    scan3_kernel<<<NB_SCAN, 256>>>();
    fill_kernel<<<NB_E, 256>>>(ei, ew);

    // join: agg1 needs both CSR (s0) and gemm1 (s1)
    cudaStreamWaitEvent(0, evB, 0);
    agg_kernel<false><<<N_NODES / 8, 256>>>(b1, batch);
    gemm_mma<true><<<NB_G, 256, GEMM_SMEM_BYTES>>>(nullptr);
    agg_kernel<true><<<N_NODES / 8, 256>>>(b2, batch);

    final_kernel<<<N_GR, 128>>>(Wh, bh, batch, out);
}

// round 11
// speedup vs baseline: 1.4932x; 1.4932x over previous
#include <cuda_runtime.h>
#include <cuda_bf16.h>
#include <cstdint>

#define N_NODES 50000
#define N_EDGES 800000
#define D       128
#define N_GR    64
#define NB_SCAN 196   // ceil(50000/256)

// -------- device scratch (no allocations allowed) --------
__device__ unsigned long long g_dcnt[N_NODES];   // fixed-point deg (low48) + count (high16)
__device__ float    g_dinv[N_NODES];
__device__ int      g_cnt [N_NODES];
__device__ int      g_off [N_NODES + 1];
__device__ int      g_bsum[256];
__device__ int      g_rank[N_EDGES];        // rank of edge within its target node
__device__ uint2    g_edge[N_EDGES];        // {src, norm-bits} per CSR slot
__device__ uint32_t g_bufA[N_NODES * 64];   // GEMM output, bf16x2-packed (gathered)
__device__ uint32_t g_bufB[N_NODES * 64];   // h1, bf16x2-packed (read seq. by GEMM2)
__device__ float    g_pool[N_GR * D];
__device__ float    g_wr1[128 * 128];       // tf32-rounded W1 ([k][n])
__device__ float    g_wr2[128 * 128];       // tf32-rounded W2 ([k][n])

#define FIXSCALE 268435456.0f               // 2^28

// ---------------- helpers ----------------
__device__ __forceinline__ float tf32r(float x) {
    uint32_t u;
    asm("cvt.rna.tf32.f32 %0, %1;" : "=r"(u) : "f"(x));
    return __uint_as_float(u);
}

__device__ __forceinline__ uint32_t packbf(float x, float y) {
    __nv_bfloat162 h = __floats2bfloat162_rn(x, y);
    return *reinterpret_cast<uint32_t*>(&h);
}

__device__ __forceinline__ float4 u2f4(uint2 u) {
    __nv_bfloat162 lo = *reinterpret_cast<__nv_bfloat162*>(&u.x);
    __nv_bfloat162 hi = *reinterpret_cast<__nv_bfloat162*>(&u.y);
    float2 a = __bfloat1622float2(lo);
    float2 b = __bfloat1622float2(hi);
    return make_float4(a.x, a.y, b.x, b.y);
}

__device__ __forceinline__ void mma_tf32(float* c, const uint32_t* a, const uint32_t* b) {
    asm volatile("mma.sync.aligned.m16n8k8.row.col.f32.tf32.tf32.f32 "
                 "{%0,%1,%2,%3}, {%4,%5,%6,%7}, {%8,%9}, {%0,%1,%2,%3};"
                 : "+f"(c[0]), "+f"(c[1]), "+f"(c[2]), "+f"(c[3])
                 : "r"(a[0]), "r"(a[1]), "r"(a[2]), "r"(a[3]),
                   "r"(b[0]), "r"(b[1]));
}

// -------- init accumulators + tf32-round weights (runs every replay) --------
__global__ void init_kernel(const float* __restrict__ W1,
                            const float* __restrict__ W2) {
    int i = blockIdx.x * blockDim.x + threadIdx.x;
    if (i < N_NODES) g_dcnt[i] = 0ULL;
    if (i < 128 * 128) { g_wr1[i] = tf32r(W1[i]); g_wr2[i] = tf32r(W2[i]); }
    if (i < N_GR * D) g_pool[i] = 0.0f;
}

// -------- per-edge: one 64-bit atomic; returned old value gives the rank ----
__global__ void edge_deg_kernel(const int* __restrict__ ei,
                                const float* __restrict__ ew) {
    int e = blockIdx.x * blockDim.x + threadIdx.x;
    if (e >= N_EDGES) return;
    int c = ei[N_EDGES + e];          // target node
    unsigned long long v = (1ULL << 48)
        | (unsigned long long)(long long)llrintf(ew[e] * FIXSCALE);
    unsigned long long old = atomicAdd(&g_dcnt[c], v);
    g_rank[e] = (int)(old >> 48);
}

// -------- scan1 fused with dinv: extract counts, dinv, block sums --------
__global__ void scan1_kernel() {
    __shared__ int s[256];
    int t = threadIdx.x;
    int i = blockIdx.x * 256 + t;
    int v = 0;
    if (i < N_NODES) {
        unsigned long long p = g_dcnt[i];
        v = (int)(p >> 48);
        g_cnt[i] = v;
        float deg = 1.0f + (float)(long long)(p & 0xFFFFFFFFFFFFULL) * (1.0f / FIXSCALE);
        g_dinv[i] = rsqrtf(deg);
    }
    s[t] = v;
    __syncthreads();
    for (int d = 128; d > 0; d >>= 1) {
        if (t < d) s[t] += s[t + d];
        __syncthreads();
    }
    if (t == 0) g_bsum[blockIdx.x] = s[0];
}

__global__ void scan2_kernel() {
    __shared__ int s[256];
    int t = threadIdx.x;
    int v = (t < NB_SCAN) ? g_bsum[t] : 0;
    s[t] = v;
    __syncthreads();
    for (int d = 1; d < 256; d <<= 1) {
        int u = (t >= d) ? s[t - d] : 0;
        __syncthreads();
        s[t] += u;
        __syncthreads();
    }
    if (t < NB_SCAN) g_bsum[t] = s[t] - v;
}

__global__ void scan3_kernel() {
    __shared__ int s[256];
    int t = threadIdx.x;
    int i = blockIdx.x * 256 + t;
    int v = (i < N_NODES) ? g_cnt[i] : 0;
    s[t] = v;
    __syncthreads();
    for (int d = 1; d < 256; d <<= 1) {
        int u = (t >= d) ? s[t - d] : 0;
        __syncthreads();
        s[t] += u;
        __syncthreads();
    }
    int base = g_bsum[blockIdx.x];
    if (i < N_NODES) g_off[i] = base + s[t] - v;
    if (i == N_NODES - 1) g_off[N_NODES] = base + s[t];
}

// -------- fill CSR: atomic-free using precomputed ranks --------
__global__ void fill_kernel(const int* __restrict__ ei,
                            const float* __restrict__ ew) {
    int e = blockIdx.x * blockDim.x + threadIdx.x;
    if (e >= N_EDGES) return;
    int r = ei[e];
    int c = ei[N_EDGES + e];
    int pos = g_off[c] + g_rank[e];
    float nrm = g_dinv[r] * ew[e] * g_dinv[c];
    g_edge[pos] = make_uint2((uint32_t)r, __float_as_uint(nrm));
}

// -------- tf32 mma.sync GEMM: g_bufA(bf16)[64-tile,128] = X-tile @ W --------
#define BM 64
#define XS_STRIDE 132
#define GEMM_SMEM_BYTES ((BM + 128) * XS_STRIDE * 4)

template <bool BF>
__global__ __launch_bounds__(256, 2) void gemm_mma(const float* __restrict__ Xext) {
    extern __shared__ float sh[];
    float* Xs = sh;                       // [64][132]
    float* Ws = sh + BM * XS_STRIDE;      // [128][132]  (W[k][n])

    const float* Wr = BF ? g_wr2 : g_wr1;

    const int tid = threadIdx.x;
    const int rowBase = blockIdx.x * BM;

#pragma unroll
    for (int i = 0; i < 8; i++) {
        int q = tid + 256 * i;            // 0..2047
        int r = q >> 5, c4 = q & 31;
        int rg = rowBase + r; if (rg >= N_NODES) rg = N_NODES - 1;
        float4 v;
        if (BF) {
            v = u2f4(reinterpret_cast<const uint2*>(g_bufB)[rg * 32 + c4]);
        } else {
            v = reinterpret_cast<const float4*>(Xext)[rg * 32 + c4];
        }
        float* d = &Xs[r * XS_STRIDE + c4 * 4];
        d[0] = tf32r(v.x); d[1] = tf32r(v.y); d[2] = tf32r(v.z); d[3] = tf32r(v.w);
    }
    const float4* W4 = reinterpret_cast<const float4*>(Wr);
#pragma unroll
    for (int i = 0; i < 16; i++) {
        int q = tid + 256 * i;            // 0..4095
        int r = q >> 5, c4 = q & 31;
        *reinterpret_cast<float4*>(&Ws[r * XS_STRIDE + c4 * 4]) = W4[q];
    }
    __syncthreads();

    const int lane = tid & 31, wid = tid >> 5;
    const int g = lane >> 2, t = lane & 3;
    const int mw = (wid >> 2) * 32;       // warp row offset (0/32)
    const int nw = (wid & 3) * 32;        // warp col offset (0/32/64/96)

    float c[2][4][4];
#pragma unroll
    for (int mt = 0; mt < 2; mt++)
#pragma unroll
        for (int nt = 0; nt < 4; nt++)
#pragma unroll
            for (int j = 0; j < 4; j++) c[mt][nt][j] = 0.f;

#pragma unroll 4
    for (int k0 = 0; k0 < 128; k0 += 8) {
        uint32_t a[2][4], b[4][2];
#pragma unroll
        for (int mt = 0; mt < 2; mt++) {
            const float* base = &Xs[(mw + mt * 16 + g) * XS_STRIDE + k0 + t];
            a[mt][0] = __float_as_uint(base[0]);
            a[mt][1] = __float_as_uint(base[8 * XS_STRIDE]);
            a[mt][2] = __float_as_uint(base[4]);
            a[mt][3] = __float_as_uint(base[8 * XS_STRIDE + 4]);
        }
#pragma unroll
        for (int nt = 0; nt < 4; nt++) {
            const float* bb = &Ws[(k0 + t) * XS_STRIDE + nw + nt * 8 + g];
            b[nt][0] = __float_as_uint(bb[0]);
            b[nt][1] = __float_as_uint(bb[4 * XS_STRIDE]);
        }
#pragma unroll
        for (int mt = 0; mt < 2; mt++)
#pragma unroll
            for (int nt = 0; nt < 4; nt++)
                mma_tf32(c[mt][nt], a[mt], b[nt]);
    }

#pragma unroll
    for (int mt = 0; mt < 2; mt++) {
        int row = rowBase + mw + mt * 16 + g;
#pragma unroll
        for (int nt = 0; nt < 4; nt++) {
            int ci = ((nw + nt * 8) >> 1) + t;      // bf16x2 column index
            if (row < N_NODES)
                g_bufA[row * 64 + ci] = packbf(c[mt][nt][0], c[mt][nt][1]);
            if (row + 8 < N_NODES)
                g_bufA[(row + 8) * 64 + ci] = packbf(c[mt][nt][2], c[mt][nt][3]);
        }
    }
}

#define AGG_FMA(W_, V_)                                             \
    acc.x = fmaf((W_), (V_).x, acc.x); acc.y = fmaf((W_), (V_).y, acc.y); \
    acc.z = fmaf((W_), (V_).z, acc.z); acc.w = fmaf((W_), (V_).w, acc.w);

// -------- aggregation: warp per node; gathers bf16 rows (unroll 4) --------
// (round-9 proven shape: uint2 per lane, float4 acc — do not perturb)
template <bool POOL>
__global__ __launch_bounds__(256) void agg_kernel(const float* __restrict__ bias,
                                                  const int* __restrict__ batch) {
    const int node = blockIdx.x * 8 + (threadIdx.x >> 5);
    const int lane = threadIdx.x & 31;
    const uint2* in2 = reinterpret_cast<const uint2*>(g_bufA);

    float di = g_dinv[node];
    float s2 = di * di;
    float4 av = u2f4(in2[node * 32 + lane]);
    float4 acc = make_float4(s2 * av.x, s2 * av.y, s2 * av.z, s2 * av.w);

    int e  = g_off[node];
    int e1 = g_off[node + 1];
    for (; e + 3 < e1; e += 4) {
        uint2 m0 = g_edge[e],   m1 = g_edge[e+1];
        uint2 m2 = g_edge[e+2], m3 = g_edge[e+3];
        uint2 r0 = in2[m0.x * 32 + lane];
        uint2 r1 = in2[m1.x * 32 + lane];
        uint2 r2 = in2[m2.x * 32 + lane];
        uint2 r3 = in2[m3.x * 32 + lane];
        float4 v0 = u2f4(r0), v1 = u2f4(r1), v2 = u2f4(r2), v3 = u2f4(r3);
        AGG_FMA(__uint_as_float(m0.y), v0);
        AGG_FMA(__uint_as_float(m1.y), v1);
        AGG_FMA(__uint_as_float(m2.y), v2);
        AGG_FMA(__uint_as_float(m3.y), v3);
    }
    for (; e < e1; e++) {
        uint2 m = g_edge[e];
        float4 v = u2f4(in2[m.x * 32 + lane]);
        AGG_FMA(__uint_as_float(m.y), v);
    }

    float4 b = reinterpret_cast<const float4*>(bias)[lane];
    acc.x = fmaxf(acc.x + b.x, 0.f);
    acc.y = fmaxf(acc.y + b.y, 0.f);
    acc.z = fmaxf(acc.z + b.z, 0.f);
    acc.w = fmaxf(acc.w + b.w, 0.f);

    if (POOL) {
        int g = batch[node];
        float* p = &g_pool[g * D + lane * 4];
        atomicAdd(p + 0, acc.x);
        atomicAdd(p + 1, acc.y);
        atomicAdd(p + 2, acc.z);
        atomicAdd(p + 3, acc.w);
    } else {
        reinterpret_cast<uint2*>(g_bufB)[node * 32 + lane] =
            make_uint2(packbf(acc.x, acc.y), packbf(acc.z, acc.w));
    }
}

// -------- head: count via binary search on sorted batch (no atomics) --------
__global__ void final_kernel(const float* __restrict__ Wh,
                             const float* __restrict__ bh,
                             const int* __restrict__ batch,
                             float* __restrict__ out) {
    __shared__ float red[128];
    const int g = blockIdx.x;
    const int t = threadIdx.x;

    int lo = 0, hi = N_NODES;
    while (lo < hi) { int m = (lo + hi) >> 1; if (batch[m] < g) lo = m + 1; else hi = m; }
    int start = lo;
    hi = N_NODES;
    while (lo < hi) { int m = (lo + hi) >> 1; if (batch[m] < g + 1) lo = m + 1; else hi = m; }
    float c = fmaxf((float)(lo - start), 1.0f);

    float v = (g_pool[g * D + t] / c) * Wh[t];
    red[t] = v;
    __syncthreads();
    for (int s = 64; s > 0; s >>= 1) {
        if (t < s) red[t] += red[t + s];
        __syncthreads();
    }
    if (t == 0) out[g] = red[0] + bh[0];
}

extern "C" void kernel_launch(void* const* d_in, const int* in_sizes, int n_in,
                              void* d_out, int out_size) {
    const float* x     = (const float*)d_in[0];
    const float* ew    = (const float*)d_in[1];
    const float* W1    = (const float*)d_in[2];
    const float* b1    = (const float*)d_in[3];
    const float* W2    = (const float*)d_in[4];
    const float* b2    = (const float*)d_in[5];
    const float* Wh    = (const float*)d_in[6];
    const float* bh    = (const float*)d_in[7];
    const int*   ei    = (const int*)d_in[8];
    const int*   batch = (const int*)d_in[9];
    float*       out   = (float*)d_out;

    const int NB_N = (N_NODES + 255) / 256;   // 196
    const int NB_E = (N_EDGES + 255) / 256;   // 3125
    const int NB_G = (N_NODES + BM - 1) / BM; // 782

    static bool ready = false;
    static cudaStream_t s1;
    static cudaEvent_t evA, evB;
    if (!ready) {
        cudaFuncSetAttribute(gemm_mma<false>, cudaFuncAttributeMaxDynamicSharedMemorySize,
                             GEMM_SMEM_BYTES);
        cudaFuncSetAttribute(gemm_mma<true>, cudaFuncAttributeMaxDynamicSharedMemorySize,
                             GEMM_SMEM_BYTES);
        cudaStreamCreateWithFlags(&s1, cudaStreamNonBlocking);
        cudaEventCreateWithFlags(&evA, cudaEventDisableTiming);
        cudaEventCreateWithFlags(&evB, cudaEventDisableTiming);
        ready = true;
    }

    // s0 = legacy default stream (the one being captured)
    init_kernel<<<NB_N, 256>>>(W1, W2);
    cudaEventRecord(evA, 0);

    // branch: layer-1 GEMM on s1, concurrent with CSR build on s0
    cudaStreamWaitEvent(s1, evA, 0);
    gemm_mma<false><<<NB_G, 256, GEMM_SMEM_BYTES, s1>>>(x);
    cudaEventRecord(evB, s1);

    edge_deg_kernel<<<NB_E, 256>>>(ei, ew);
    scan1_kernel<<<NB_SCAN, 256>>>();
    scan2_kernel<<<1, 256>>>();
    scan3_kernel<<<NB_SCAN, 256>>>();
    fill_kernel<<<NB_E, 256>>>(ei, ew);

    // join: agg1 needs both CSR (s0) and gemm1 (s1)
    cudaStreamWaitEvent(0, evB, 0);
    agg_kernel<false><<<N_NODES / 8, 256>>>(b1, batch);
    gemm_mma<true><<<NB_G, 256, GEMM_SMEM_BYTES>>>(nullptr);
    agg_kernel<true><<<N_NODES / 8, 256>>>(b2, batch);

    final_kernel<<<N_GR, 128>>>(Wh, bh, batch, out);
}

// round 12
// speedup vs baseline: 1.5340x; 1.0273x over previous
#include <cuda_runtime.h>
#include <cuda_bf16.h>
#include <cstdint>

#define N_NODES 50000
#define N_EDGES 800000
#define D       128
#define N_GR    64
#define NB_SCAN 196   // ceil(50000/256)

// -------- device scratch (no allocations allowed) --------
__device__ unsigned long long g_dcnt[N_NODES];   // fixed-point deg (low48) + count (high16)
__device__ float    g_dinv[N_NODES];
__device__ int      g_cnt [N_NODES];
__device__ int      g_cur [N_NODES];
__device__ int      g_off [N_NODES + 1];
__device__ int      g_bsum[256];
__device__ uint2    g_edge[N_EDGES];        // {src, norm-bits} per CSR slot
__device__ uint32_t g_bufA[N_NODES * 64];   // GEMM output, bf16x2-packed (gathered)
__device__ uint32_t g_bufB[N_NODES * 64];   // h1, bf16x2-packed (read seq. by GEMM2)
__device__ float    g_pool[N_GR * D];
__device__ float    g_wr1[128 * 128];       // tf32-rounded W1 ([k][n])
__device__ float    g_wr2[128 * 128];       // tf32-rounded W2 ([k][n])

#define FIXSCALE 268435456.0f               // 2^28

// ---------------- helpers ----------------
__device__ __forceinline__ float tf32r(float x) {
    uint32_t u;
    asm("cvt.rna.tf32.f32 %0, %1;" : "=r"(u) : "f"(x));
    return __uint_as_float(u);
}

__device__ __forceinline__ uint32_t packbf(float x, float y) {
    __nv_bfloat162 h = __floats2bfloat162_rn(x, y);
    return *reinterpret_cast<uint32_t*>(&h);
}

__device__ __forceinline__ float4 u2f4(uint2 u) {
    __nv_bfloat162 lo = *reinterpret_cast<__nv_bfloat162*>(&u.x);
    __nv_bfloat162 hi = *reinterpret_cast<__nv_bfloat162*>(&u.y);
    float2 a = __bfloat1622float2(lo);
    float2 b = __bfloat1622float2(hi);
    return make_float4(a.x, a.y, b.x, b.y);
}

__device__ __forceinline__ void mma_tf32(float* c, const uint32_t* a, const uint32_t* b) {
    asm volatile("mma.sync.aligned.m16n8k8.row.col.f32.tf32.tf32.f32 "
                 "{%0,%1,%2,%3}, {%4,%5,%6,%7}, {%8,%9}, {%0,%1,%2,%3};"
                 : "+f"(c[0]), "+f"(c[1]), "+f"(c[2]), "+f"(c[3])
                 : "r"(a[0]), "r"(a[1]), "r"(a[2]), "r"(a[3]),
                   "r"(b[0]), "r"(b[1]));
}

// -------- init_b: tf32-round weights + zero pool (gemm1 depends on this) ----
__global__ void init_b_kernel(const float* __restrict__ W1,
                              const float* __restrict__ W2) {
    int i = blockIdx.x * blockDim.x + threadIdx.x;
    if (i < 128 * 128) { g_wr1[i] = tf32r(W1[i]); g_wr2[i] = tf32r(W2[i]); }
    if (i < N_GR * D) g_pool[i] = 0.0f;
}

// -------- init_a: zero CSR accumulators (edge_deg/fill depend on this) ------
__global__ void init_a_kernel() {
    int i = blockIdx.x * blockDim.x + threadIdx.x;
    if (i < N_NODES) { g_dcnt[i] = 0ULL; g_cur[i] = 0; }
}

// -------- per-edge: one 64-bit atomic = fixed-point deg sum + count --------
__global__ void edge_deg_kernel(const int* __restrict__ ei,
                                const float* __restrict__ ew) {
    int e = blockIdx.x * blockDim.x + threadIdx.x;
    if (e >= N_EDGES) return;
    int c = ei[N_EDGES + e];          // target node
    unsigned long long v = (1ULL << 48)
        | (unsigned long long)(long long)llrintf(ew[e] * FIXSCALE);
    atomicAdd(&g_dcnt[c], v);
}

// -------- scan1 fused with dinv: extract counts, dinv, block sums --------
__global__ void scan1_kernel() {
    __shared__ int s[256];
    int t = threadIdx.x;
    int i = blockIdx.x * 256 + t;
    int v = 0;
    if (i < N_NODES) {
        unsigned long long p = g_dcnt[i];
        v = (int)(p >> 48);
        g_cnt[i] = v;
        float deg = 1.0f + (float)(long long)(p & 0xFFFFFFFFFFFFULL) * (1.0f / FIXSCALE);
        g_dinv[i] = rsqrtf(deg);
    }
    s[t] = v;
    __syncthreads();
    for (int d = 128; d > 0; d >>= 1) {
        if (t < d) s[t] += s[t + d];
        __syncthreads();
    }
    if (t == 0) g_bsum[blockIdx.x] = s[0];
}

__global__ void scan2_kernel() {
    __shared__ int s[256];
    int t = threadIdx.x;
    int v = (t < NB_SCAN) ? g_bsum[t] : 0;
    s[t] = v;
    __syncthreads();
    for (int d = 1; d < 256; d <<= 1) {
        int u = (t >= d) ? s[t - d] : 0;
        __syncthreads();
        s[t] += u;
        __syncthreads();
    }
    if (t < NB_SCAN) g_bsum[t] = s[t] - v;
}

__global__ void scan3_kernel() {
    __shared__ int s[256];
    int t = threadIdx.x;
    int i = blockIdx.x * 256 + t;
    int v = (i < N_NODES) ? g_cnt[i] : 0;
    s[t] = v;
    __syncthreads();
    for (int d = 1; d < 256; d <<= 1) {
        int u = (t >= d) ? s[t - d] : 0;
        __syncthreads();
        s[t] += u;
        __syncthreads();
    }
    int base = g_bsum[blockIdx.x];
    if (i < N_NODES) g_off[i] = base + s[t] - v;
    if (i == N_NODES - 1) g_off[N_NODES] = base + s[t];
}

// -------- fill CSR: fused {src, norm} records (round-9 proven shape) --------
__global__ void fill_kernel(const int* __restrict__ ei,
                            const float* __restrict__ ew) {
    int e = blockIdx.x * blockDim.x + threadIdx.x;
    if (e >= N_EDGES) return;
    int r = ei[e];
    int c = ei[N_EDGES + e];
    int pos = g_off[c] + atomicAdd(&g_cur[c], 1);
    float nrm = g_dinv[r] * ew[e] * g_dinv[c];
    g_edge[pos] = make_uint2((uint32_t)r, __float_as_uint(nrm));
}

// -------- tf32 mma.sync GEMM: g_bufA(bf16)[64-tile,128] = X-tile @ W --------
#define BM 64
#define XS_STRIDE 132
#define GEMM_SMEM_BYTES ((BM + 128) * XS_STRIDE * 4)

template <bool BF>
__global__ __launch_bounds__(256, 2) void gemm_mma(const float* __restrict__ Xext) {
    extern __shared__ float sh[];
    float* Xs = sh;                       // [64][132]
    float* Ws = sh + BM * XS_STRIDE;      // [128][132]  (W[k][n])

    const float* Wr = BF ? g_wr2 : g_wr1;

    const int tid = threadIdx.x;
    const int rowBase = blockIdx.x * BM;

#pragma unroll
    for (int i = 0; i < 8; i++) {
        int q = tid + 256 * i;            // 0..2047
        int r = q >> 5, c4 = q & 31;
        int rg = rowBase + r; if (rg >= N_NODES) rg = N_NODES - 1;
        float4 v;
        if (BF) {
            v = u2f4(reinterpret_cast<const uint2*>(g_bufB)[rg * 32 + c4]);
        } else {
            v = reinterpret_cast<const float4*>(Xext)[rg * 32 + c4];
        }
        float* d = &Xs[r * XS_STRIDE + c4 * 4];
        d[0] = tf32r(v.x); d[1] = tf32r(v.y); d[2] = tf32r(v.z); d[3] = tf32r(v.w);
    }
    const float4* W4 = reinterpret_cast<const float4*>(Wr);
#pragma unroll
    for (int i = 0; i < 16; i++) {
        int q = tid + 256 * i;            // 0..4095
        int r = q >> 5, c4 = q & 31;
        *reinterpret_cast<float4*>(&Ws[r * XS_STRIDE + c4 * 4]) = W4[q];
    }
    __syncthreads();

    const int lane = tid & 31, wid = tid >> 5;
    const int g = lane >> 2, t = lane & 3;
    const int mw = (wid >> 2) * 32;       // warp row offset (0/32)
    const int nw = (wid & 3) * 32;        // warp col offset (0/32/64/96)

    float c[2][4][4];
#pragma unroll
    for (int mt = 0; mt < 2; mt++)
#pragma unroll
        for (int nt = 0; nt < 4; nt++)
#pragma unroll
            for (int j = 0; j < 4; j++) c[mt][nt][j] = 0.f;

#pragma unroll 4
    for (int k0 = 0; k0 < 128; k0 += 8) {
        uint32_t a[2][4], b[4][2];
#pragma unroll
        for (int mt = 0; mt < 2; mt++) {
            const float* base = &Xs[(mw + mt * 16 + g) * XS_STRIDE + k0 + t];
            a[mt][0] = __float_as_uint(base[0]);
            a[mt][1] = __float_as_uint(base[8 * XS_STRIDE]);
            a[mt][2] = __float_as_uint(base[4]);
            a[mt][3] = __float_as_uint(base[8 * XS_STRIDE + 4]);
        }
#pragma unroll
        for (int nt = 0; nt < 4; nt++) {
            const float* bb = &Ws[(k0 + t) * XS_STRIDE + nw + nt * 8 + g];
            b[nt][0] = __float_as_uint(bb[0]);
            b[nt][1] = __float_as_uint(bb[4 * XS_STRIDE]);
        }
#pragma unroll
        for (int mt = 0; mt < 2; mt++)
#pragma unroll
            for (int nt = 0; nt < 4; nt++)
                mma_tf32(c[mt][nt], a[mt], b[nt]);
    }

#pragma unroll
    for (int mt = 0; mt < 2; mt++) {
        int row = rowBase + mw + mt * 16 + g;
#pragma unroll
        for (int nt = 0; nt < 4; nt++) {
            int ci = ((nw + nt * 8) >> 1) + t;      // bf16x2 column index
            if (row < N_NODES)
                g_bufA[row * 64 + ci] = packbf(c[mt][nt][0], c[mt][nt][1]);
            if (row + 8 < N_NODES)
                g_bufA[(row + 8) * 64 + ci] = packbf(c[mt][nt][2], c[mt][nt][3]);
        }
    }
}

#define AGG_FMA(W_, V_)                                             \
    acc.x = fmaf((W_), (V_).x, acc.x); acc.y = fmaf((W_), (V_).y, acc.y); \
    acc.z = fmaf((W_), (V_).z, acc.z); acc.w = fmaf((W_), (V_).w, acc.w);

// -------- aggregation: warp per node; gathers bf16 rows (unroll 4) --------
// (round-9 proven shape: uint2 per lane, float4 acc — do not perturb)
template <bool POOL>
__global__ __launch_bounds__(256) void agg_kernel(const float* __restrict__ bias,
                                                  const int* __restrict__ batch) {
    const int node = blockIdx.x * 8 + (threadIdx.x >> 5);
    const int lane = threadIdx.x & 31;
    const uint2* in2 = reinterpret_cast<const uint2*>(g_bufA);

    float di = g_dinv[node];
    float s2 = di * di;
    float4 av = u2f4(in2[node * 32 + lane]);
    float4 acc = make_float4(s2 * av.x, s2 * av.y, s2 * av.z, s2 * av.w);

    int e  = g_off[node];
    int e1 = g_off[node + 1];
    for (; e + 3 < e1; e += 4) {
        uint2 m0 = g_edge[e],   m1 = g_edge[e+1];
        uint2 m2 = g_edge[e+2], m3 = g_edge[e+3];
        uint2 r0 = in2[m0.x * 32 + lane];
        uint2 r1 = in2[m1.x * 32 + lane];
        uint2 r2 = in2[m2.x * 32 + lane];
        uint2 r3 = in2[m3.x * 32 + lane];
        float4 v0 = u2f4(r0), v1 = u2f4(r1), v2 = u2f4(r2), v3 = u2f4(r3);
        AGG_FMA(__uint_as_float(m0.y), v0);
        AGG_FMA(__uint_as_float(m1.y), v1);
        AGG_FMA(__uint_as_float(m2.y), v2);
        AGG_FMA(__uint_as_float(m3.y), v3);
    }
    for (; e < e1; e++) {
        uint2 m = g_edge[e];
        float4 v = u2f4(in2[m.x * 32 + lane]);
        AGG_FMA(__uint_as_float(m.y), v);
    }

    float4 b = reinterpret_cast<const float4*>(bias)[lane];
    acc.x = fmaxf(acc.x + b.x, 0.f);
    acc.y = fmaxf(acc.y + b.y, 0.f);
    acc.z = fmaxf(acc.z + b.z, 0.f);
    acc.w = fmaxf(acc.w + b.w, 0.f);

    if (POOL) {
        int g = batch[node];
        float* p = &g_pool[g * D + lane * 4];
        atomicAdd(p + 0, acc.x);
        atomicAdd(p + 1, acc.y);
        atomicAdd(p + 2, acc.z);
        atomicAdd(p + 3, acc.w);
    } else {
        reinterpret_cast<uint2*>(g_bufB)[node * 32 + lane] =
            make_uint2(packbf(acc.x, acc.y), packbf(acc.z, acc.w));
    }
}

// -------- head: count via binary search on sorted batch (no atomics) --------
__global__ void final_kernel(const float* __restrict__ Wh,
                             const float* __restrict__ bh,
                             const int* __restrict__ batch,
                             float* __restrict__ out) {
    __shared__ float red[128];
    const int g = blockIdx.x;
    const int t = threadIdx.x;

    int lo = 0, hi = N_NODES;
    while (lo < hi) { int m = (lo + hi) >> 1; if (batch[m] < g) lo = m + 1; else hi = m; }
    int start = lo;
    hi = N_NODES;
    while (lo < hi) { int m = (lo + hi) >> 1; if (batch[m] < g + 1) lo = m + 1; else hi = m; }
    float c = fmaxf((float)(lo - start), 1.0f);

    float v = (g_pool[g * D + t] / c) * Wh[t];
    red[t] = v;
    __syncthreads();
    for (int s = 64; s > 0; s >>= 1) {
        if (t < s) red[t] += red[t + s];
        __syncthreads();
    }
    if (t == 0) out[g] = red[0] + bh[0];
}

extern "C" void kernel_launch(void* const* d_in, const int* in_sizes, int n_in,
                              void* d_out, int out_size) {
    const float* x     = (const float*)d_in[0];
    const float* ew    = (const float*)d_in[1];
    const float* W1    = (const float*)d_in[2];
    const float* b1    = (const float*)d_in[3];
    const float* W2    = (const float*)d_in[4];
    const float* b2    = (const float*)d_in[5];
    const float* Wh    = (const float*)d_in[6];
    const float* bh    = (const float*)d_in[7];
    const int*   ei    = (const int*)d_in[8];
    const int*   batch = (const int*)d_in[9];
    float*       out   = (float*)d_out;

    const int NB_N = (N_NODES + 255) / 256;   // 196
    const int NB_E = (N_EDGES + 255) / 256;   // 3125
    const int NB_G = (N_NODES + BM - 1) / BM; // 782

    static bool ready = false;
    static cudaStream_t s1;
    static cudaEvent_t evA, evB;
    if (!ready) {
        cudaFuncSetAttribute(gemm_mma<false>, cudaFuncAttributeMaxDynamicSharedMemorySize,
                             GEMM_SMEM_BYTES);
        cudaFuncSetAttribute(gemm_mma<true>, cudaFuncAttributeMaxDynamicSharedMemorySize,
                             GEMM_SMEM_BYTES);
        cudaStreamCreateWithFlags(&s1, cudaStreamNonBlocking);
        cudaEventCreateWithFlags(&evA, cudaEventDisableTiming);
        cudaEventCreateWithFlags(&evB, cudaEventDisableTiming);
        ready = true;
    }

    // launch index 0: weights+pool (gemm1's only dependency)
    init_b_kernel<<<64, 256>>>(W1, W2);
    cudaEventRecord(evA, 0);

    // launch index 1: CSR accumulator zeroing (s0, before edge_deg)
    init_a_kernel<<<NB_N, 256>>>();

    // launch index 2: layer-1 GEMM on s1, overlapped with CSR build
    cudaStreamWaitEvent(s1, evA, 0);
    gemm_mma<false><<<NB_G, 256, GEMM_SMEM_BYTES, s1>>>(x);
    cudaEventRecord(evB, s1);

    // launch index 3: edge_deg — lands in the ncu capture slot this round
    edge_deg_kernel<<<NB_E, 256>>>(ei, ew);
    scan1_kernel<<<NB_SCAN, 256>>>();
    scan2_kernel<<<1, 256>>>();
    scan3_kernel<<<NB_SCAN, 256>>>();
    fill_kernel<<<NB_E, 256>>>(ei, ew);

    // join: agg1 needs both CSR (s0) and gemm1 (s1)
    cudaStreamWaitEvent(0, evB, 0);
    agg_kernel<false><<<N_NODES / 8, 256>>>(b1, batch);
    gemm_mma<true><<<NB_G, 256, GEMM_SMEM_BYTES>>>(nullptr);
    agg_kernel<true><<<N_NODES / 8, 256>>>(b2, batch);

    final_kernel<<<N_GR, 128>>>(Wh, bh, batch, out);
}